// round 14
// baseline (speedup 1.0000x reference)
#include <cuda_runtime.h>
#include <cuda_fp16.h>
#include <math.h>
#include <stdint.h>

#define Bz 2
#define Sz 4096
#define Dz 1024
#define Fz 4096
#define Mz (Bz * Sz)
#define NCH 256
#define CLEN 16

// ------------------------- scratch --------------------------------------
__device__ __align__(256) __half g_P16[(size_t)Mz * 4096];
__device__ __align__(256) float  g_Pa [(size_t)Mz * 2048];
__device__ __align__(256) __half g_Yoh[(size_t)Mz * Dz];
__device__ __align__(256) float g_U [(size_t)Mz * Dz];
__device__ __align__(256) float g_O2[(size_t)Mz * Dz];
__device__ __align__(256) __half g_xh[(size_t)Mz * Dz];
__device__ __align__(256) __half g_yh[(size_t)Mz * Dz];
__device__ __align__(256) __half g_uh[(size_t)Mz * Dz];
__device__ __align__(256) __half g_Hh[(size_t)Mz * Fz];
__device__ __align__(256) __half g_Wc[(size_t)6144 * Dz];
__device__ __align__(256) __half g_Wo[(size_t)Dz * Dz];
__device__ __align__(256) __half g_W1[(size_t)Fz * Dz];
__device__ __align__(256) __half g_W2[(size_t)Dz * Fz];
__device__ float s_apr[524288], s_api[524288], s_hr[524288], s_hi[524288];
__device__ float s_cr[524288], s_ci[524288];

// ------------------------- asm helpers ----------------------------------
__device__ __forceinline__ uint32_t smem_u32(const void* p) {
    uint32_t a;
    asm("{ .reg .u64 t; cvta.to.shared.u64 t, %1; cvt.u32.u64 %0, t; }" : "=r"(a) : "l"(p));
    return a;
}
__device__ __forceinline__ void cp16(uint32_t dst, const void* src) {
    asm volatile("cp.async.cg.shared.global [%0], [%1], 16;" :: "r"(dst), "l"(src) : "memory");
}
__device__ __forceinline__ void ldsm4(uint32_t* r, uint32_t a) {
    asm volatile("ldmatrix.sync.aligned.m8n8.x4.shared.b16 {%0,%1,%2,%3}, [%4];"
                 : "=r"(r[0]), "=r"(r[1]), "=r"(r[2]), "=r"(r[3]) : "r"(a));
}
__device__ __forceinline__ void mma16816(float* c, const uint32_t* a, uint32_t b0, uint32_t b1) {
    asm volatile(
        "mma.sync.aligned.m16n8k16.row.col.f32.f16.f16.f32 "
        "{%0,%1,%2,%3}, {%4,%5,%6,%7}, {%8,%9}, {%0,%1,%2,%3};"
        : "+f"(c[0]), "+f"(c[1]), "+f"(c[2]), "+f"(c[3])
        : "r"(a[0]), "r"(a[1]), "r"(a[2]), "r"(a[3]), "r"(b0), "r"(b1));
}
__device__ __forceinline__ uint32_t swz(int m, int ch) {
    return (uint32_t)((m << 7) + ((ch ^ (m & 7)) << 4));
}
__device__ __forceinline__ float tanh_fast(float x) {
    float r;
    asm("tanh.approx.f32 %0, %1;" : "=f"(r) : "f"(x));
    return r;
}

// ------------------------- fp16 GEMM (R11 mainloop, frozen) --------------
#define STG 32768
#define GEMM_SMEM (3 * STG)

__global__ void __launch_bounds__(128, 2) gemm_mma(
    const __half* __restrict__ Ah, const __half* __restrict__ Bh,
    const float* __restrict__ bias,
    float* __restrict__ Cf, int ldcf,
    __half* __restrict__ Ch, int ldch, int choff, int split,
    int K, int act, int mode)
{
    extern __shared__ __align__(1024) char dsm[];
    const uint32_t smb = smem_u32(dsm);
    const int tid = threadIdx.x;
    const int bm = blockIdx.y * 128, bn = blockIdx.x * 128;
    const int wid = tid >> 5, L = tid & 31;
    const int wm = (wid >> 1) * 64;
    const int wn = (wid & 1) * 64;

    float acc[4][8][4];
#pragma unroll
    for (int i = 0; i < 4; i++)
#pragma unroll
        for (int j = 0; j < 8; j++)
#pragma unroll
            for (int q = 0; q < 4; q++) acc[i][j][q] = 0.f;

    const int matid = L >> 3;
    const int rA = (matid & 1) * 8 + (L & 7);
    const int cA = matid >> 1;
    const int rB = (L >> 4) * 8 + (L & 7);
    const int cB = (L >> 3) & 1;

    const int nkc = K / 64;
    auto load_stage = [&](int st, int kc) {
        uint32_t sb = smb + st * STG;
        size_t kb = (size_t)kc * 64;
#pragma unroll
        for (int t = 0; t < 8; t++) {
            int id = t * 128 + tid;
            int m = id >> 3, ch = id & 7;
            uint32_t dst = swz(m, ch);
            cp16(sb + dst,         Ah + (size_t)(bm + m) * K + kb + ch * 8);
            cp16(sb + 16384 + dst, Bh + (size_t)(bn + m) * K + kb + ch * 8);
        }
    };

    load_stage(0, 0);
    asm volatile("cp.async.commit_group;" ::: "memory");
    load_stage(1, 1);
    asm volatile("cp.async.commit_group;" ::: "memory");

    int st = 0;
    for (int kc = 0; kc < nkc; kc++) {
        asm volatile("cp.async.wait_group 1;" ::: "memory");
        __syncthreads();
        uint32_t sb = smb + st * STG;
        uint32_t sAh = sb, sBh = sb + 16384;
#pragma unroll
        for (int ks = 0; ks < 4; ks++) {
            uint32_t ah[4][4], bh[4][4];
#pragma unroll
            for (int mt = 0; mt < 4; mt++)
                ldsm4(ah[mt], sAh + swz(wm + mt * 16 + rA, ks * 2 + cA));
#pragma unroll
            for (int bt = 0; bt < 4; bt++)
                ldsm4(bh[bt], sBh + swz(wn + bt * 16 + rB, ks * 2 + cB));
#pragma unroll
            for (int mt = 0; mt < 4; mt++)
#pragma unroll
                for (int nt = 0; nt < 8; nt++) {
                    int bt = nt >> 1, j = (nt & 1) * 2;
                    mma16816(acc[mt][nt], ah[mt], bh[bt][j], bh[bt][j + 1]);
                }
        }
        if (kc + 2 < nkc) load_stage((st + 2) % 3, kc + 2);
        asm volatile("cp.async.commit_group;" ::: "memory");
        st = (st + 1) % 3;
    }

    // epilogue
#pragma unroll
    for (int mt = 0; mt < 4; mt++)
#pragma unroll
        for (int nt = 0; nt < 8; nt++) {
            int c0 = bn + wn + nt * 8 + (L & 3) * 2;
            float b0 = (act > 0) ? bias[c0] : 0.f;
            float b1 = (act > 0) ? bias[c0 + 1] : 0.f;
#pragma unroll
            for (int h = 0; h < 2; h++) {
                int row = bm + wm + mt * 16 + (L >> 2) + h * 8;
                float v0 = acc[mt][nt][h * 2 + 0] + b0;
                float v1 = acc[mt][nt][h * 2 + 1] + b1;
                if (act == 2) {
                    float t0 = v0 * v0 * v0, t1 = v1 * v1 * v1;
                    v0 = 0.5f * v0 * (1.f + tanh_fast(0.7978845608028654f * (v0 + 0.044715f * t0)));
                    v1 = 0.5f * v1 * (1.f + tanh_fast(0.7978845608028654f * (v1 + 0.044715f * t1)));
                }
                if (mode == 3) {
                    if (c0 < 3072) {
                        __half2 hh; hh.x = __float2half_rn(v0); hh.y = __float2half_rn(v1);
                        *reinterpret_cast<__half2*>(Ch + (size_t)row * 4096 + c0) = hh;
                    } else if (c0 < 5120) {
                        *reinterpret_cast<float2*>(Cf + (size_t)row * 2048 + (c0 - 3072)) =
                            make_float2(v0, v1);
                    } else {
                        __half2 hh; hh.x = __float2half_rn(v0); hh.y = __float2half_rn(v1);
                        *reinterpret_cast<__half2*>(Ch + (size_t)row * 4096 + (c0 - 2048)) = hh;
                    }
                } else {
                    if (Cf && c0 < split) {
                        size_t idx = (size_t)row * ldcf + c0;
                        *reinterpret_cast<float2*>(Cf + idx) = make_float2(v0, v1);
                    }
                    if (Ch && c0 >= split) {
                        size_t idx = (size_t)row * ldch + c0 + choff;
                        __half2 hh;
                        hh.x = __float2half_rn(v0);
                        hh.y = __float2half_rn(v1);
                        *reinterpret_cast<__half2*>(Ch + idx) = hh;
                    }
                }
            }
        }
}

// ------------------------- fused weight convert ---------------------------
struct WJob { const float* src; __half* th; int K; int N; int blk0; };
struct WJobs { WJob j[8]; };

__global__ void wconv_all(WJobs js) {
    __shared__ float t[32][33];
    int blk = blockIdx.x;
    int w = 0;
#pragma unroll
    for (int i = 1; i < 8; i++) if (blk >= js.j[i].blk0) w = i;
    const WJob& J = js.j[w];
    int local = blk - J.blk0;
    int nbn = J.N >> 5;
    int n0 = (local % nbn) << 5, k0 = (local / nbn) << 5;
    int tx = threadIdx.x, ty = threadIdx.y;
#pragma unroll
    for (int q = 0; q < 4; q++)
        t[ty + q * 8][tx] = J.src[(size_t)(k0 + ty + q * 8) * J.N + n0 + tx];
    __syncthreads();
#pragma unroll
    for (int q = 0; q < 4; q++)
        J.th[(size_t)(n0 + ty + q * 8) * J.K + k0 + tx] = __float2half_rn(t[tx][ty + q * 8]);
}

// ------------------------- small kernels ---------------------------------
__global__ void conv_h(const float* __restrict__ in, __half* __restrict__ hi, size_t n4) {
    size_t i = (size_t)blockIdx.x * blockDim.x + threadIdx.x;
    if (i >= n4) return;
    float4 v = ((const float4*)in)[i];
    __half2 a, b;
    a.x = __float2half_rn(v.x); a.y = __float2half_rn(v.y);
    b.x = __float2half_rn(v.z); b.y = __float2half_rn(v.w);
    ((__half2*)hi)[i * 2]     = a;
    ((__half2*)hi)[i * 2 + 1] = b;
}

__global__ void scan_p1(const __half* __restrict__ P16, const float* __restrict__ Pa) {
    int idx = blockIdx.x * blockDim.x + threadIdx.x;   // 524288
    int ch = idx & 2047, ck = idx >> 11;               // ck 0..255
    int b = ch >> 10, d = ch & 1023;
    size_t row0 = (size_t)(b * Sz + ck * CLEN);
    float hr = 0, hi = 0, pr = 1, pi = 0;
    for (int t = 0; t < CLEN; t++) {
        size_t r16 = (row0 + t) * 4096;
        size_t ra  = (row0 + t) * 2048;
        float ar = Pa[ra + d], ai = Pa[ra + 1024 + d];
        float kv = __half2float(P16[r16 + 1024 + d]) * __half2float(P16[r16 + 2048 + d]);
        float mag = sqrtf(fmaf(ar, ar, ai * ai));
        float s = 1.f / (1.f + __expf(-mag));
        float inv = s / fmaxf(mag, 1e-30f);
        float arr = ar * inv, aii = ai * inv;
        float nhr = fmaf(arr, hr, fmaf(-aii, hi, kv));
        float nhi = fmaf(arr, hi, aii * hr);
        hr = nhr; hi = nhi;
        float npr = arr * pr - aii * pi, npi = arr * pi + aii * pr;
        pr = npr; pi = npi;
    }
    s_apr[idx] = pr; s_api[idx] = pi; s_hr[idx] = hr; s_hi[idx] = hi;
}

__global__ void scan_p2() {
    int ch = blockIdx.x * blockDim.x + threadIdx.x;
    if (ch >= 2048) return;
    float cr = 0, ci = 0;
    for (int ck = 0; ck < NCH; ck++) {
        int i = ck * 2048 + ch;
        s_cr[i] = cr; s_ci[i] = ci;
        float pr = s_apr[i], pi = s_api[i];
        float ncr = fmaf(pr, cr, -pi * ci) + s_hr[i];
        float nci = fmaf(pr, ci,  pi * cr) + s_hi[i];
        cr = ncr; ci = nci;
    }
}

__global__ void scan_p3(const __half* __restrict__ P16, const float* __restrict__ Pa,
                        __half* __restrict__ yh) {
    int idx = blockIdx.x * blockDim.x + threadIdx.x;
    int ch = idx & 2047, ck = idx >> 11;
    int b = ch >> 10, d = ch & 1023;
    size_t row0 = (size_t)(b * Sz + ck * CLEN);
    float hr = s_cr[idx], hi = s_ci[idx];
    for (int t = 0; t < CLEN; t++) {
        size_t r16 = (row0 + t) * 4096;
        size_t ra  = (row0 + t) * 2048;
        float ar = Pa[ra + d], ai = Pa[ra + 1024 + d];
        float kv = __half2float(P16[r16 + 1024 + d]) * __half2float(P16[r16 + 2048 + d]);
        float mag = sqrtf(fmaf(ar, ar, ai * ai));
        float s = 1.f / (1.f + __expf(-mag));
        float inv = s / fmaxf(mag, 1e-30f);
        float arr = ar * inv, aii = ai * inv;
        float nhr = fmaf(arr, hr, fmaf(-aii, hi, kv));
        float nhi = fmaf(arr, hi, aii * hr);
        hr = nhr; hi = nhi;
        float g = __half2float(P16[r16 + 3072 + d]);
        float sil = g / (1.f + __expf(-g));
        float q = __half2float(P16[r16 + d]);
        yh[(row0 + t) * Dz + d] = __float2half_rn(q * hr * sil);
    }
}

// LN with fp16 main input (Yo path)
__global__ __launch_bounds__(256) void add_ln_h(
    const __half* __restrict__ xh16, const float* __restrict__ res,
    const float* __restrict__ scale, const float* __restrict__ bias,
    float* __restrict__ out, __half* __restrict__ oh)
{
    __shared__ float red[8];
    int row = blockIdx.x, tid = threadIdx.x;
    const __half* xr = xh16 + (size_t)row * Dz;
    const float* rr = res + (size_t)row * Dz;
    float vals[4], sum = 0.f;
#pragma unroll
    for (int j = 0; j < 4; j++) {
        vals[j] = __half2float(xr[tid + j * 256]) + rr[tid + j * 256];
        sum += vals[j];
    }
#pragma unroll
    for (int o = 16; o > 0; o >>= 1) sum += __shfl_xor_sync(~0u, sum, o);
    if ((tid & 31) == 0) red[tid >> 5] = sum;
    __syncthreads();
    float tot = 0.f;
#pragma unroll
    for (int w = 0; w < 8; w++) tot += red[w];
    float mean = tot * (1.f / Dz);
    float vs = 0.f;
#pragma unroll
    for (int j = 0; j < 4; j++) { float dd = vals[j] - mean; vs += dd * dd; }
#pragma unroll
    for (int o = 16; o > 0; o >>= 1) vs += __shfl_xor_sync(~0u, vs, o);
    __syncthreads();
    if ((tid & 31) == 0) red[tid >> 5] = vs;
    __syncthreads();
    float vt = 0.f;
#pragma unroll
    for (int w = 0; w < 8; w++) vt += red[w];
    float rstd = rsqrtf(vt * (1.f / Dz) + 1e-6f);
#pragma unroll
    for (int j = 0; j < 4; j++) {
        int col = tid + j * 256;
        float v = (vals[j] - mean) * rstd * scale[col] + bias[col];
        size_t idx = (size_t)row * Dz + col;
        out[idx] = v;
        if (oh) oh[idx] = __float2half_rn(v);
    }
}

__global__ __launch_bounds__(256) void add_ln_kernel(
    const float* __restrict__ x, const float* __restrict__ res,
    const float* __restrict__ scale, const float* __restrict__ bias,
    float* __restrict__ out, __half* __restrict__ oh)
{
    __shared__ float red[8];
    int row = blockIdx.x, tid = threadIdx.x;
    const float* xr = x + (size_t)row * Dz;
    const float* rr = res + (size_t)row * Dz;
    float vals[4], sum = 0.f;
#pragma unroll
    for (int j = 0; j < 4; j++) { vals[j] = xr[tid + j * 256] + rr[tid + j * 256]; sum += vals[j]; }
#pragma unroll
    for (int o = 16; o > 0; o >>= 1) sum += __shfl_xor_sync(~0u, sum, o);
    if ((tid & 31) == 0) red[tid >> 5] = sum;
    __syncthreads();
    float tot = 0.f;
#pragma unroll
    for (int w = 0; w < 8; w++) tot += red[w];
    float mean = tot * (1.f / Dz);
    float vs = 0.f;
#pragma unroll
    for (int j = 0; j < 4; j++) { float dd = vals[j] - mean; vs += dd * dd; }
#pragma unroll
    for (int o = 16; o > 0; o >>= 1) vs += __shfl_xor_sync(~0u, vs, o);
    __syncthreads();
    if ((tid & 31) == 0) red[tid >> 5] = vs;
    __syncthreads();
    float vt = 0.f;
#pragma unroll
    for (int w = 0; w < 8; w++) vt += red[w];
    float rstd = rsqrtf(vt * (1.f / Dz) + 1e-6f);
#pragma unroll
    for (int j = 0; j < 4; j++) {
        int col = tid + j * 256;
        float v = (vals[j] - mean) * rstd * scale[col] + bias[col];
        size_t idx = (size_t)row * Dz + col;
        out[idx] = v;
        if (oh) oh[idx] = __float2half_rn(v);
    }
}

// ------------------------- host ------------------------------------------
static void rungemm(const __half* Ah, const __half* Bh, int Nblk, int K,
                    const float* bias,
                    float* Cf, int ldcf, __half* Ch, int ldch, int choff, int split,
                    int act, int mode) {
    dim3 g(Nblk / 128, Mz / 128);
    gemm_mma<<<g, 128, GEMM_SMEM>>>(Ah, Bh, bias, Cf, ldcf, Ch, ldch, choff, split, K, act, mode);
}

extern "C" void kernel_launch(void* const* d_in, const int* in_sizes, int n_in,
                              void* d_out, int out_size)
{
    const float* x    = (const float*)d_in[0];
    const float* Wq   = (const float*)d_in[1];
    const float* Wk   = (const float*)d_in[2];
    const float* Wv   = (const float*)d_in[3];
    const float* Wa   = (const float*)d_in[4];
    const float* Wg   = (const float*)d_in[5];
    const float* Wo   = (const float*)d_in[6];
    const float* ln1s = (const float*)d_in[7];
    const float* ln1b = (const float*)d_in[8];
    const float* W1   = (const float*)d_in[9];
    const float* b1   = (const float*)d_in[10];
    const float* W2   = (const float*)d_in[11];
    const float* b2   = (const float*)d_in[12];
    const float* ln2s = (const float*)d_in[13];
    const float* ln2b = (const float*)d_in[14];
    float* out = (float*)d_out;

    static int inited = 0;
    if (!inited) {
        cudaFuncSetAttribute(gemm_mma, cudaFuncAttributeMaxDynamicSharedMemorySize, GEMM_SMEM);
        inited = 1;
    }

    float *Pa, *U, *O2;
    __half *P16, *Yoh, *xh, *yh, *uh, *Hh, *Wc, *WoP, *W1P, *W2P;
    cudaGetSymbolAddress((void**)&P16, g_P16);
    cudaGetSymbolAddress((void**)&Pa,  g_Pa);
    cudaGetSymbolAddress((void**)&Yoh, g_Yoh);
    cudaGetSymbolAddress((void**)&U,  g_U);
    cudaGetSymbolAddress((void**)&O2, g_O2);
    cudaGetSymbolAddress((void**)&xh, g_xh);
    cudaGetSymbolAddress((void**)&yh, g_yh);
    cudaGetSymbolAddress((void**)&uh, g_uh);
    cudaGetSymbolAddress((void**)&Hh, g_Hh);
    cudaGetSymbolAddress((void**)&Wc,  g_Wc);
    cudaGetSymbolAddress((void**)&WoP, g_Wo);
    cudaGetSymbolAddress((void**)&W1P, g_W1);
    cudaGetSymbolAddress((void**)&W2P, g_W2);

    WJobs js;
    js.j[0] = { Wq, Wc,                       Dz, Dz,     0 };
    js.j[1] = { Wk, Wc + 1024 * 1024,         Dz, Dz,     1024 };
    js.j[2] = { Wv, Wc + 2048 * 1024,         Dz, Dz,     2048 };
    js.j[3] = { Wa, Wc + 3072 * 1024,         Dz, 2 * Dz, 3072 };
    js.j[4] = { Wg, Wc + (size_t)5120 * 1024, Dz, Dz,     5120 };
    js.j[5] = { Wo, WoP, Dz, Dz,  6144 };
    js.j[6] = { W1, W1P, Dz, Fz,  7168 };
    js.j[7] = { W2, W2P, Fz, Dz, 11264 };
    wconv_all<<<15360, dim3(32, 8)>>>(js);                                      // 0
    conv_h<<<(Mz * Dz / 4 + 255) / 256, 256>>>(x, xh, (size_t)Mz * Dz / 4);     // 1
    rungemm(xh, Wc, 6144, Dz, nullptr, Pa, 0, P16, 0, 0, 0, 0, 3);              // 2
    scan_p1<<<2048, 256>>>(P16, Pa);                                            // 3
    scan_p2<<<8, 256>>>();                                                      // 4
    scan_p3<<<2048, 256>>>(P16, Pa, yh);                                        // 5
    rungemm(yh, WoP, 1024, Dz, nullptr, nullptr, 0, Yoh, 1024, 0, 0, 0, 0);     // 6
    add_ln_h<<<Mz, 256>>>(Yoh, x, ln1s, ln1b, U, uh);                           // 7
    rungemm(uh, W1P, 4096, Dz, b1, nullptr, 0, Hh, 4096, 0, 0, 2, 0);           // 8
    rungemm(Hh, W2P, 1024, Fz, b2, O2, 1024, nullptr, 0, 0, 1 << 30, 1, 0);     // 9
    add_ln_kernel<<<Mz, 256>>>(O2, U, ln2s, ln2b, out, nullptr);                // 10
}

// round 15
// speedup vs baseline: 1.0442x; 1.0442x over previous
#include <cuda_runtime.h>
#include <cuda_fp16.h>
#include <math.h>
#include <stdint.h>

#define Bz 2
#define Sz 4096
#define Dz 1024
#define Fz 4096
#define Mz (Bz * Sz)
#define NCH 128
#define CLEN 32

// ------------------------- scratch --------------------------------------
__device__ __align__(256) __half g_P16[(size_t)Mz * 4096];
__device__ __align__(256) float  g_Pa [(size_t)Mz * 2048];
__device__ __align__(256) __half g_Yoh[(size_t)Mz * Dz];
__device__ __align__(256) float g_U [(size_t)Mz * Dz];
__device__ __align__(256) __half g_O2h[(size_t)Mz * Dz];
__device__ __align__(256) __half g_xh[(size_t)Mz * Dz];
__device__ __align__(256) __half g_yh[(size_t)Mz * Dz];
__device__ __align__(256) __half g_uh[(size_t)Mz * Dz];
__device__ __align__(256) __half g_Hh[(size_t)Mz * Fz];
__device__ __align__(256) __half g_Wc[(size_t)6144 * Dz];
__device__ __align__(256) __half g_Wo[(size_t)Dz * Dz];
__device__ __align__(256) __half g_W1[(size_t)Fz * Dz];
__device__ __align__(256) __half g_W2[(size_t)Dz * Fz];
__device__ float s_apr[262144], s_api[262144], s_hr[262144], s_hi[262144];
__device__ float s_cr[262144], s_ci[262144];

// ------------------------- asm helpers ----------------------------------
__device__ __forceinline__ uint32_t smem_u32(const void* p) {
    uint32_t a;
    asm("{ .reg .u64 t; cvta.to.shared.u64 t, %1; cvt.u32.u64 %0, t; }" : "=r"(a) : "l"(p));
    return a;
}
__device__ __forceinline__ void cp16(uint32_t dst, const void* src) {
    asm volatile("cp.async.cg.shared.global [%0], [%1], 16;" :: "r"(dst), "l"(src) : "memory");
}
__device__ __forceinline__ void ldsm4(uint32_t* r, uint32_t a) {
    asm volatile("ldmatrix.sync.aligned.m8n8.x4.shared.b16 {%0,%1,%2,%3}, [%4];"
                 : "=r"(r[0]), "=r"(r[1]), "=r"(r[2]), "=r"(r[3]) : "r"(a));
}
__device__ __forceinline__ void mma16816(float* c, const uint32_t* a, uint32_t b0, uint32_t b1) {
    asm volatile(
        "mma.sync.aligned.m16n8k16.row.col.f32.f16.f16.f32 "
        "{%0,%1,%2,%3}, {%4,%5,%6,%7}, {%8,%9}, {%0,%1,%2,%3};"
        : "+f"(c[0]), "+f"(c[1]), "+f"(c[2]), "+f"(c[3])
        : "r"(a[0]), "r"(a[1]), "r"(a[2]), "r"(a[3]), "r"(b0), "r"(b1));
}
__device__ __forceinline__ uint32_t swz(int m, int ch) {
    return (uint32_t)((m << 7) + ((ch ^ (m & 7)) << 4));
}
__device__ __forceinline__ float tanh_fast(float x) {
    float r;
    asm("tanh.approx.f32 %0, %1;" : "=f"(r) : "f"(x));
    return r;
}

// ------------------------- fp16 GEMM (R11 mainloop, frozen) --------------
#define STG 32768
#define GEMM_SMEM (3 * STG)

__global__ void __launch_bounds__(128, 2) gemm_mma(
    const __half* __restrict__ Ah, const __half* __restrict__ Bh,
    const float* __restrict__ bias,
    float* __restrict__ Cf, int ldcf,
    __half* __restrict__ Ch, int ldch, int choff, int split,
    int K, int act, int mode)
{
    extern __shared__ __align__(1024) char dsm[];
    const uint32_t smb = smem_u32(dsm);
    const int tid = threadIdx.x;
    const int bm = blockIdx.y * 128, bn = blockIdx.x * 128;
    const int wid = tid >> 5, L = tid & 31;
    const int wm = (wid >> 1) * 64;
    const int wn = (wid & 1) * 64;

    float acc[4][8][4];
#pragma unroll
    for (int i = 0; i < 4; i++)
#pragma unroll
        for (int j = 0; j < 8; j++)
#pragma unroll
            for (int q = 0; q < 4; q++) acc[i][j][q] = 0.f;

    const int matid = L >> 3;
    const int rA = (matid & 1) * 8 + (L & 7);
    const int cA = matid >> 1;
    const int rB = (L >> 4) * 8 + (L & 7);
    const int cB = (L >> 3) & 1;

    const int nkc = K / 64;
    auto load_stage = [&](int st, int kc) {
        uint32_t sb = smb + st * STG;
        size_t kb = (size_t)kc * 64;
#pragma unroll
        for (int t = 0; t < 8; t++) {
            int id = t * 128 + tid;
            int m = id >> 3, ch = id & 7;
            uint32_t dst = swz(m, ch);
            cp16(sb + dst,         Ah + (size_t)(bm + m) * K + kb + ch * 8);
            cp16(sb + 16384 + dst, Bh + (size_t)(bn + m) * K + kb + ch * 8);
        }
    };

    load_stage(0, 0);
    asm volatile("cp.async.commit_group;" ::: "memory");
    load_stage(1, 1);
    asm volatile("cp.async.commit_group;" ::: "memory");

    int st = 0;
    for (int kc = 0; kc < nkc; kc++) {
        asm volatile("cp.async.wait_group 1;" ::: "memory");
        __syncthreads();
        uint32_t sb = smb + st * STG;
        uint32_t sAh = sb, sBh = sb + 16384;
#pragma unroll
        for (int ks = 0; ks < 4; ks++) {
            uint32_t ah[4][4], bh[4][4];
#pragma unroll
            for (int mt = 0; mt < 4; mt++)
                ldsm4(ah[mt], sAh + swz(wm + mt * 16 + rA, ks * 2 + cA));
#pragma unroll
            for (int bt = 0; bt < 4; bt++)
                ldsm4(bh[bt], sBh + swz(wn + bt * 16 + rB, ks * 2 + cB));
#pragma unroll
            for (int mt = 0; mt < 4; mt++)
#pragma unroll
                for (int nt = 0; nt < 8; nt++) {
                    int bt = nt >> 1, j = (nt & 1) * 2;
                    mma16816(acc[mt][nt], ah[mt], bh[bt][j], bh[bt][j + 1]);
                }
        }
        if (kc + 2 < nkc) load_stage((st + 2) % 3, kc + 2);
        asm volatile("cp.async.commit_group;" ::: "memory");
        st = (st + 1) % 3;
    }

    // epilogue
#pragma unroll
    for (int mt = 0; mt < 4; mt++)
#pragma unroll
        for (int nt = 0; nt < 8; nt++) {
            int c0 = bn + wn + nt * 8 + (L & 3) * 2;
            float b0 = (act > 0) ? bias[c0] : 0.f;
            float b1 = (act > 0) ? bias[c0 + 1] : 0.f;
#pragma unroll
            for (int h = 0; h < 2; h++) {
                int row = bm + wm + mt * 16 + (L >> 2) + h * 8;
                float v0 = acc[mt][nt][h * 2 + 0] + b0;
                float v1 = acc[mt][nt][h * 2 + 1] + b1;
                if (act == 2) {
                    float t0 = v0 * v0 * v0, t1 = v1 * v1 * v1;
                    v0 = 0.5f * v0 * (1.f + tanh_fast(0.7978845608028654f * (v0 + 0.044715f * t0)));
                    v1 = 0.5f * v1 * (1.f + tanh_fast(0.7978845608028654f * (v1 + 0.044715f * t1)));
                }
                if (mode == 3) {
                    if (c0 < 3072) {
                        __half2 hh; hh.x = __float2half_rn(v0); hh.y = __float2half_rn(v1);
                        *reinterpret_cast<__half2*>(Ch + (size_t)row * 4096 + c0) = hh;
                    } else if (c0 < 5120) {
                        *reinterpret_cast<float2*>(Cf + (size_t)row * 2048 + (c0 - 3072)) =
                            make_float2(v0, v1);
                    } else {
                        __half2 hh; hh.x = __float2half_rn(v0); hh.y = __float2half_rn(v1);
                        *reinterpret_cast<__half2*>(Ch + (size_t)row * 4096 + (c0 - 2048)) = hh;
                    }
                } else {
                    if (Cf && c0 < split) {
                        size_t idx = (size_t)row * ldcf + c0;
                        *reinterpret_cast<float2*>(Cf + idx) = make_float2(v0, v1);
                    }
                    if (Ch && c0 >= split) {
                        size_t idx = (size_t)row * ldch + c0 + choff;
                        __half2 hh;
                        hh.x = __float2half_rn(v0);
                        hh.y = __float2half_rn(v1);
                        *reinterpret_cast<__half2*>(Ch + idx) = hh;
                    }
                }
            }
        }
}

// ------------------------- fused weight convert ---------------------------
struct WJob { const float* src; __half* th; int K; int N; int blk0; };
struct WJobs { WJob j[8]; };

__global__ void wconv_all(WJobs js) {
    __shared__ float t[32][33];
    int blk = blockIdx.x;
    int w = 0;
#pragma unroll
    for (int i = 1; i < 8; i++) if (blk >= js.j[i].blk0) w = i;
    const WJob& J = js.j[w];
    int local = blk - J.blk0;
    int nbn = J.N >> 5;
    int n0 = (local % nbn) << 5, k0 = (local / nbn) << 5;
    int tx = threadIdx.x, ty = threadIdx.y;
#pragma unroll
    for (int q = 0; q < 4; q++)
        t[ty + q * 8][tx] = J.src[(size_t)(k0 + ty + q * 8) * J.N + n0 + tx];
    __syncthreads();
#pragma unroll
    for (int q = 0; q < 4; q++)
        J.th[(size_t)(n0 + ty + q * 8) * J.K + k0 + tx] = __float2half_rn(t[tx][ty + q * 8]);
}

// ------------------------- small kernels ---------------------------------
__global__ void conv_h(const float* __restrict__ in, __half* __restrict__ hi, size_t n4) {
    size_t i = (size_t)blockIdx.x * blockDim.x + threadIdx.x;
    if (i >= n4) return;
    float4 v = ((const float4*)in)[i];
    __half2 a, b;
    a.x = __float2half_rn(v.x); a.y = __float2half_rn(v.y);
    b.x = __float2half_rn(v.z); b.y = __float2half_rn(v.w);
    ((__half2*)hi)[i * 2]     = a;
    ((__half2*)hi)[i * 2 + 1] = b;
}

__global__ void scan_p1(const __half* __restrict__ P16, const float* __restrict__ Pa) {
    int idx = blockIdx.x * blockDim.x + threadIdx.x;   // 262144
    int ch = idx & 2047, ck = idx >> 11;               // ck 0..127
    int b = ch >> 10, d = ch & 1023;
    size_t row0 = (size_t)(b * Sz + ck * CLEN);
    float hr = 0, hi = 0, pr = 1, pi = 0;
    for (int t = 0; t < CLEN; t++) {
        size_t r16 = (row0 + t) * 4096;
        size_t ra  = (row0 + t) * 2048;
        float ar = Pa[ra + d], ai = Pa[ra + 1024 + d];
        float kv = __half2float(P16[r16 + 1024 + d]) * __half2float(P16[r16 + 2048 + d]);
        float mag = sqrtf(fmaf(ar, ar, ai * ai));
        float s = 1.f / (1.f + __expf(-mag));
        float inv = s / fmaxf(mag, 1e-30f);
        float arr = ar * inv, aii = ai * inv;
        float nhr = fmaf(arr, hr, fmaf(-aii, hi, kv));
        float nhi = fmaf(arr, hi, aii * hr);
        hr = nhr; hi = nhi;
        float npr = arr * pr - aii * pi, npi = arr * pi + aii * pr;
        pr = npr; pi = npi;
    }
    s_apr[idx] = pr; s_api[idx] = pi; s_hr[idx] = hr; s_hi[idx] = hi;
}

__global__ void scan_p2() {
    int ch = blockIdx.x * blockDim.x + threadIdx.x;
    if (ch >= 2048) return;
    float cr = 0, ci = 0;
    for (int ck = 0; ck < NCH; ck++) {
        int i = ck * 2048 + ch;
        s_cr[i] = cr; s_ci[i] = ci;
        float pr = s_apr[i], pi = s_api[i];
        float ncr = fmaf(pr, cr, -pi * ci) + s_hr[i];
        float nci = fmaf(pr, ci,  pi * cr) + s_hi[i];
        cr = ncr; ci = nci;
    }
}

__global__ void scan_p3(const __half* __restrict__ P16, const float* __restrict__ Pa,
                        __half* __restrict__ yh) {
    int idx = blockIdx.x * blockDim.x + threadIdx.x;
    int ch = idx & 2047, ck = idx >> 11;
    int b = ch >> 10, d = ch & 1023;
    size_t row0 = (size_t)(b * Sz + ck * CLEN);
    float hr = s_cr[idx], hi = s_ci[idx];
    for (int t = 0; t < CLEN; t++) {
        size_t r16 = (row0 + t) * 4096;
        size_t ra  = (row0 + t) * 2048;
        float ar = Pa[ra + d], ai = Pa[ra + 1024 + d];
        float kv = __half2float(P16[r16 + 1024 + d]) * __half2float(P16[r16 + 2048 + d]);
        float mag = sqrtf(fmaf(ar, ar, ai * ai));
        float s = 1.f / (1.f + __expf(-mag));
        float inv = s / fmaxf(mag, 1e-30f);
        float arr = ar * inv, aii = ai * inv;
        float nhr = fmaf(arr, hr, fmaf(-aii, hi, kv));
        float nhi = fmaf(arr, hi, aii * hr);
        hr = nhr; hi = nhi;
        float g = __half2float(P16[r16 + 3072 + d]);
        float sil = g / (1.f + __expf(-g));
        float q = __half2float(P16[r16 + d]);
        yh[(row0 + t) * Dz + d] = __float2half_rn(q * hr * sil);
    }
}

// LN with fp16 main input
__global__ __launch_bounds__(256) void add_ln_h(
    const __half* __restrict__ xh16, const float* __restrict__ res,
    const float* __restrict__ scale, const float* __restrict__ bias,
    float* __restrict__ out, __half* __restrict__ oh)
{
    __shared__ float red[8];
    int row = blockIdx.x, tid = threadIdx.x;
    const __half* xr = xh16 + (size_t)row * Dz;
    const float* rr = res + (size_t)row * Dz;
    float vals[4], sum = 0.f;
#pragma unroll
    for (int j = 0; j < 4; j++) {
        vals[j] = __half2float(xr[tid + j * 256]) + rr[tid + j * 256];
        sum += vals[j];
    }
#pragma unroll
    for (int o = 16; o > 0; o >>= 1) sum += __shfl_xor_sync(~0u, sum, o);
    if ((tid & 31) == 0) red[tid >> 5] = sum;
    __syncthreads();
    float tot = 0.f;
#pragma unroll
    for (int w = 0; w < 8; w++) tot += red[w];
    float mean = tot * (1.f / Dz);
    float vs = 0.f;
#pragma unroll
    for (int j = 0; j < 4; j++) { float dd = vals[j] - mean; vs += dd * dd; }
#pragma unroll
    for (int o = 16; o > 0; o >>= 1) vs += __shfl_xor_sync(~0u, vs, o);
    __syncthreads();
    if ((tid & 31) == 0) red[tid >> 5] = vs;
    __syncthreads();
    float vt = 0.f;
#pragma unroll
    for (int w = 0; w < 8; w++) vt += red[w];
    float rstd = rsqrtf(vt * (1.f / Dz) + 1e-6f);
#pragma unroll
    for (int j = 0; j < 4; j++) {
        int col = tid + j * 256;
        float v = (vals[j] - mean) * rstd * scale[col] + bias[col];
        size_t idx = (size_t)row * Dz + col;
        out[idx] = v;
        if (oh) oh[idx] = __float2half_rn(v);
    }
}

// ------------------------- host ------------------------------------------
static void rungemm(const __half* Ah, const __half* Bh, int Nblk, int K,
                    const float* bias,
                    float* Cf, int ldcf, __half* Ch, int ldch, int choff, int split,
                    int act, int mode) {
    dim3 g(Nblk / 128, Mz / 128);
    gemm_mma<<<g, 128, GEMM_SMEM>>>(Ah, Bh, bias, Cf, ldcf, Ch, ldch, choff, split, K, act, mode);
}

extern "C" void kernel_launch(void* const* d_in, const int* in_sizes, int n_in,
                              void* d_out, int out_size)
{
    const float* x    = (const float*)d_in[0];
    const float* Wq   = (const float*)d_in[1];
    const float* Wk   = (const float*)d_in[2];
    const float* Wv   = (const float*)d_in[3];
    const float* Wa   = (const float*)d_in[4];
    const float* Wg   = (const float*)d_in[5];
    const float* Wo   = (const float*)d_in[6];
    const float* ln1s = (const float*)d_in[7];
    const float* ln1b = (const float*)d_in[8];
    const float* W1   = (const float*)d_in[9];
    const float* b1   = (const float*)d_in[10];
    const float* W2   = (const float*)d_in[11];
    const float* b2   = (const float*)d_in[12];
    const float* ln2s = (const float*)d_in[13];
    const float* ln2b = (const float*)d_in[14];
    float* out = (float*)d_out;

    static int inited = 0;
    if (!inited) {
        cudaFuncSetAttribute(gemm_mma, cudaFuncAttributeMaxDynamicSharedMemorySize, GEMM_SMEM);
        inited = 1;
    }

    float *Pa, *U;
    __half *P16, *Yoh, *O2h, *xh, *yh, *uh, *Hh, *Wc, *WoP, *W1P, *W2P;
    cudaGetSymbolAddress((void**)&P16, g_P16);
    cudaGetSymbolAddress((void**)&Pa,  g_Pa);
    cudaGetSymbolAddress((void**)&Yoh, g_Yoh);
    cudaGetSymbolAddress((void**)&U,   g_U);
    cudaGetSymbolAddress((void**)&O2h, g_O2h);
    cudaGetSymbolAddress((void**)&xh, g_xh);
    cudaGetSymbolAddress((void**)&yh, g_yh);
    cudaGetSymbolAddress((void**)&uh, g_uh);
    cudaGetSymbolAddress((void**)&Hh, g_Hh);
    cudaGetSymbolAddress((void**)&Wc,  g_Wc);
    cudaGetSymbolAddress((void**)&WoP, g_Wo);
    cudaGetSymbolAddress((void**)&W1P, g_W1);
    cudaGetSymbolAddress((void**)&W2P, g_W2);

    WJobs js;
    js.j[0] = { Wq, Wc,                       Dz, Dz,     0 };
    js.j[1] = { Wk, Wc + 1024 * 1024,         Dz, Dz,     1024 };
    js.j[2] = { Wv, Wc + 2048 * 1024,         Dz, Dz,     2048 };
    js.j[3] = { Wa, Wc + 3072 * 1024,         Dz, 2 * Dz, 3072 };
    js.j[4] = { Wg, Wc + (size_t)5120 * 1024, Dz, Dz,     5120 };
    js.j[5] = { Wo, WoP, Dz, Dz,  6144 };
    js.j[6] = { W1, W1P, Dz, Fz,  7168 };
    js.j[7] = { W2, W2P, Fz, Dz, 11264 };
    wconv_all<<<15360, dim3(32, 8)>>>(js);                                      // 0
    conv_h<<<(Mz * Dz / 4 + 255) / 256, 256>>>(x, xh, (size_t)Mz * Dz / 4);     // 1
    rungemm(xh, Wc, 6144, Dz, nullptr, Pa, 0, P16, 0, 0, 0, 0, 3);              // 2
    scan_p1<<<1024, 256>>>(P16, Pa);                                            // 3
    scan_p2<<<8, 256>>>();                                                      // 4
    scan_p3<<<1024, 256>>>(P16, Pa, yh);                                        // 5
    rungemm(yh, WoP, 1024, Dz, nullptr, nullptr, 0, Yoh, 1024, 0, 0, 0, 0);     // 6
    add_ln_h<<<Mz, 256>>>(Yoh, x, ln1s, ln1b, U, uh);                           // 7
    rungemm(uh, W1P, 4096, Dz, b1, nullptr, 0, Hh, 4096, 0, 0, 2, 0);           // 8
    rungemm(Hh, W2P, 1024, Fz, b2, nullptr, 0, O2h, 1024, 0, 0, 1, 0);          // 9
    add_ln_h<<<Mz, 256>>>(O2h, U, ln2s, ln2b, out, nullptr);                    // 10
}

// round 16
// speedup vs baseline: 1.0466x; 1.0024x over previous
#include <cuda_runtime.h>
#include <cuda_fp16.h>
#include <math.h>
#include <stdint.h>

#define Bz 2
#define Sz 4096
#define Dz 1024
#define Fz 4096
#define Mz (Bz * Sz)
#define NCH 128
#define CLEN 32

// ------------------------- scratch --------------------------------------
__device__ __align__(256) __half g_P16[(size_t)Mz * 4096];
__device__ __align__(256) float  g_Pa [(size_t)Mz * 2048];
__device__ __align__(256) __half g_Yoh[(size_t)Mz * Dz];
__device__ __align__(256) __half g_O2h[(size_t)Mz * Dz];
__device__ __align__(256) __half g_xh[(size_t)Mz * Dz];
__device__ __align__(256) __half g_yh[(size_t)Mz * Dz];
__device__ __align__(256) __half g_uh[(size_t)Mz * Dz];
__device__ __align__(256) __half g_Hh[(size_t)Mz * Fz];
__device__ __align__(256) __half g_Wc[(size_t)6144 * Dz];
__device__ __align__(256) __half g_Wo[(size_t)Dz * Dz];
__device__ __align__(256) __half g_W1[(size_t)Fz * Dz];
__device__ __align__(256) __half g_W2[(size_t)Dz * Fz];
__device__ float s_apr[262144], s_api[262144], s_hr[262144], s_hi[262144];
__device__ float s_cr[262144], s_ci[262144];

// ------------------------- asm helpers ----------------------------------
__device__ __forceinline__ uint32_t smem_u32(const void* p) {
    uint32_t a;
    asm("{ .reg .u64 t; cvta.to.shared.u64 t, %1; cvt.u32.u64 %0, t; }" : "=r"(a) : "l"(p));
    return a;
}
__device__ __forceinline__ void cp16(uint32_t dst, const void* src) {
    asm volatile("cp.async.cg.shared.global [%0], [%1], 16;" :: "r"(dst), "l"(src) : "memory");
}
__device__ __forceinline__ void ldsm4(uint32_t* r, uint32_t a) {
    asm volatile("ldmatrix.sync.aligned.m8n8.x4.shared.b16 {%0,%1,%2,%3}, [%4];"
                 : "=r"(r[0]), "=r"(r[1]), "=r"(r[2]), "=r"(r[3]) : "r"(a));
}
__device__ __forceinline__ void mma16816(float* c, const uint32_t* a, uint32_t b0, uint32_t b1) {
    asm volatile(
        "mma.sync.aligned.m16n8k16.row.col.f32.f16.f16.f32 "
        "{%0,%1,%2,%3}, {%4,%5,%6,%7}, {%8,%9}, {%0,%1,%2,%3};"
        : "+f"(c[0]), "+f"(c[1]), "+f"(c[2]), "+f"(c[3])
        : "r"(a[0]), "r"(a[1]), "r"(a[2]), "r"(a[3]), "r"(b0), "r"(b1));
}
__device__ __forceinline__ uint32_t swz(int m, int ch) {
    return (uint32_t)((m << 7) + ((ch ^ (m & 7)) << 4));
}
__device__ __forceinline__ float tanh_fast(float x) {
    float r;
    asm("tanh.approx.f32 %0, %1;" : "=f"(r) : "f"(x));
    return r;
}

// ------------------------- fp16 GEMM (R11 mainloop, frozen) --------------
#define STG 32768
#define GEMM_SMEM (3 * STG)

__global__ void __launch_bounds__(128, 2) gemm_mma(
    const __half* __restrict__ Ah, const __half* __restrict__ Bh,
    const float* __restrict__ bias,
    float* __restrict__ Cf, int ldcf,
    __half* __restrict__ Ch, int ldch, int choff, int split,
    int K, int act, int mode)
{
    extern __shared__ __align__(1024) char dsm[];
    const uint32_t smb = smem_u32(dsm);
    const int tid = threadIdx.x;
    const int bm = blockIdx.y * 128, bn = blockIdx.x * 128;
    const int wid = tid >> 5, L = tid & 31;
    const int wm = (wid >> 1) * 64;
    const int wn = (wid & 1) * 64;

    float acc[4][8][4];
#pragma unroll
    for (int i = 0; i < 4; i++)
#pragma unroll
        for (int j = 0; j < 8; j++)
#pragma unroll
            for (int q = 0; q < 4; q++) acc[i][j][q] = 0.f;

    const int matid = L >> 3;
    const int rA = (matid & 1) * 8 + (L & 7);
    const int cA = matid >> 1;
    const int rB = (L >> 4) * 8 + (L & 7);
    const int cB = (L >> 3) & 1;

    const int nkc = K / 64;
    auto load_stage = [&](int st, int kc) {
        uint32_t sb = smb + st * STG;
        size_t kb = (size_t)kc * 64;
#pragma unroll
        for (int t = 0; t < 8; t++) {
            int id = t * 128 + tid;
            int m = id >> 3, ch = id & 7;
            uint32_t dst = swz(m, ch);
            cp16(sb + dst,         Ah + (size_t)(bm + m) * K + kb + ch * 8);
            cp16(sb + 16384 + dst, Bh + (size_t)(bn + m) * K + kb + ch * 8);
        }
    };

    load_stage(0, 0);
    asm volatile("cp.async.commit_group;" ::: "memory");
    load_stage(1, 1);
    asm volatile("cp.async.commit_group;" ::: "memory");

    int st = 0;
    for (int kc = 0; kc < nkc; kc++) {
        asm volatile("cp.async.wait_group 1;" ::: "memory");
        __syncthreads();
        uint32_t sb = smb + st * STG;
        uint32_t sAh = sb, sBh = sb + 16384;
#pragma unroll
        for (int ks = 0; ks < 4; ks++) {
            uint32_t ah[4][4], bh[4][4];
#pragma unroll
            for (int mt = 0; mt < 4; mt++)
                ldsm4(ah[mt], sAh + swz(wm + mt * 16 + rA, ks * 2 + cA));
#pragma unroll
            for (int bt = 0; bt < 4; bt++)
                ldsm4(bh[bt], sBh + swz(wn + bt * 16 + rB, ks * 2 + cB));
#pragma unroll
            for (int mt = 0; mt < 4; mt++)
#pragma unroll
                for (int nt = 0; nt < 8; nt++) {
                    int bt = nt >> 1, j = (nt & 1) * 2;
                    mma16816(acc[mt][nt], ah[mt], bh[bt][j], bh[bt][j + 1]);
                }
        }
        if (kc + 2 < nkc) load_stage((st + 2) % 3, kc + 2);
        asm volatile("cp.async.commit_group;" ::: "memory");
        st = (st + 1) % 3;
    }

    // epilogue
#pragma unroll
    for (int mt = 0; mt < 4; mt++)
#pragma unroll
        for (int nt = 0; nt < 8; nt++) {
            int c0 = bn + wn + nt * 8 + (L & 3) * 2;
            float b0 = (act > 0) ? bias[c0] : 0.f;
            float b1 = (act > 0) ? bias[c0 + 1] : 0.f;
#pragma unroll
            for (int h = 0; h < 2; h++) {
                int row = bm + wm + mt * 16 + (L >> 2) + h * 8;
                float v0 = acc[mt][nt][h * 2 + 0] + b0;
                float v1 = acc[mt][nt][h * 2 + 1] + b1;
                if (act == 2) {
                    float t0 = v0 * v0 * v0, t1 = v1 * v1 * v1;
                    v0 = 0.5f * v0 * (1.f + tanh_fast(0.7978845608028654f * (v0 + 0.044715f * t0)));
                    v1 = 0.5f * v1 * (1.f + tanh_fast(0.7978845608028654f * (v1 + 0.044715f * t1)));
                }
                if (mode == 3) {
                    if (c0 < 3072) {
                        __half2 hh; hh.x = __float2half_rn(v0); hh.y = __float2half_rn(v1);
                        *reinterpret_cast<__half2*>(Ch + (size_t)row * 4096 + c0) = hh;
                    } else if (c0 < 5120) {
                        *reinterpret_cast<float2*>(Cf + (size_t)row * 2048 + (c0 - 3072)) =
                            make_float2(v0, v1);
                    } else {
                        __half2 hh; hh.x = __float2half_rn(v0); hh.y = __float2half_rn(v1);
                        *reinterpret_cast<__half2*>(Ch + (size_t)row * 4096 + (c0 - 2048)) = hh;
                    }
                } else {
                    if (Cf && c0 < split) {
                        size_t idx = (size_t)row * ldcf + c0;
                        *reinterpret_cast<float2*>(Cf + idx) = make_float2(v0, v1);
                    }
                    if (Ch && c0 >= split) {
                        size_t idx = (size_t)row * ldch + c0 + choff;
                        __half2 hh;
                        hh.x = __float2half_rn(v0);
                        hh.y = __float2half_rn(v1);
                        *reinterpret_cast<__half2*>(Ch + idx) = hh;
                    }
                }
            }
        }
}

// ------------------------- fused weight convert ---------------------------
struct WJob { const float* src; __half* th; int K; int N; int blk0; };
struct WJobs { WJob j[8]; };

__global__ void wconv_all(WJobs js) {
    __shared__ float t[32][33];
    int blk = blockIdx.x;
    int w = 0;
#pragma unroll
    for (int i = 1; i < 8; i++) if (blk >= js.j[i].blk0) w = i;
    const WJob& J = js.j[w];
    int local = blk - J.blk0;
    int nbn = J.N >> 5;
    int n0 = (local % nbn) << 5, k0 = (local / nbn) << 5;
    int tx = threadIdx.x, ty = threadIdx.y;
#pragma unroll
    for (int q = 0; q < 4; q++)
        t[ty + q * 8][tx] = J.src[(size_t)(k0 + ty + q * 8) * J.N + n0 + tx];
    __syncthreads();
#pragma unroll
    for (int q = 0; q < 4; q++)
        J.th[(size_t)(n0 + ty + q * 8) * J.K + k0 + tx] = __float2half_rn(t[tx][ty + q * 8]);
}

// ------------------------- small kernels ---------------------------------
__global__ void conv_h(const float* __restrict__ in, __half* __restrict__ hi, size_t n4) {
    size_t i = (size_t)blockIdx.x * blockDim.x + threadIdx.x;
    if (i >= n4) return;
    float4 v = ((const float4*)in)[i];
    __half2 a, b;
    a.x = __float2half_rn(v.x); a.y = __float2half_rn(v.y);
    b.x = __float2half_rn(v.z); b.y = __float2half_rn(v.w);
    ((__half2*)hi)[i * 2]     = a;
    ((__half2*)hi)[i * 2 + 1] = b;
}

__global__ void scan_p1(const __half* __restrict__ P16, const float* __restrict__ Pa) {
    int idx = blockIdx.x * blockDim.x + threadIdx.x;
    int ch = idx & 2047, ck = idx >> 11;
    int b = ch >> 10, d = ch & 1023;
    size_t row0 = (size_t)(b * Sz + ck * CLEN);
    float hr = 0, hi = 0, pr = 1, pi = 0;
    for (int t = 0; t < CLEN; t++) {
        size_t r16 = (row0 + t) * 4096;
        size_t ra  = (row0 + t) * 2048;
        float ar = Pa[ra + d], ai = Pa[ra + 1024 + d];
        float kv = __half2float(P16[r16 + 1024 + d]) * __half2float(P16[r16 + 2048 + d]);
        float mag = sqrtf(fmaf(ar, ar, ai * ai));
        float s = 1.f / (1.f + __expf(-mag));
        float inv = s / fmaxf(mag, 1e-30f);
        float arr = ar * inv, aii = ai * inv;
        float nhr = fmaf(arr, hr, fmaf(-aii, hi, kv));
        float nhi = fmaf(arr, hi, aii * hr);
        hr = nhr; hi = nhi;
        float npr = arr * pr - aii * pi, npi = arr * pi + aii * pr;
        pr = npr; pi = npi;
    }
    s_apr[idx] = pr; s_api[idx] = pi; s_hr[idx] = hr; s_hi[idx] = hi;
}

__global__ void scan_p2() {
    int ch = blockIdx.x * blockDim.x + threadIdx.x;
    if (ch >= 2048) return;
    float cr = 0, ci = 0;
    for (int ck = 0; ck < NCH; ck++) {
        int i = ck * 2048 + ch;
        s_cr[i] = cr; s_ci[i] = ci;
        float pr = s_apr[i], pi = s_api[i];
        float ncr = fmaf(pr, cr, -pi * ci) + s_hr[i];
        float nci = fmaf(pr, ci,  pi * cr) + s_hi[i];
        cr = ncr; ci = nci;
    }
}

__global__ void scan_p3(const __half* __restrict__ P16, const float* __restrict__ Pa,
                        __half* __restrict__ yh) {
    int idx = blockIdx.x * blockDim.x + threadIdx.x;
    int ch = idx & 2047, ck = idx >> 11;
    int b = ch >> 10, d = ch & 1023;
    size_t row0 = (size_t)(b * Sz + ck * CLEN);
    float hr = s_cr[idx], hi = s_ci[idx];
    for (int t = 0; t < CLEN; t++) {
        size_t r16 = (row0 + t) * 4096;
        size_t ra  = (row0 + t) * 2048;
        float ar = Pa[ra + d], ai = Pa[ra + 1024 + d];
        float kv = __half2float(P16[r16 + 1024 + d]) * __half2float(P16[r16 + 2048 + d]);
        float mag = sqrtf(fmaf(ar, ar, ai * ai));
        float s = 1.f / (1.f + __expf(-mag));
        float inv = s / fmaxf(mag, 1e-30f);
        float arr = ar * inv, aii = ai * inv;
        float nhr = fmaf(arr, hr, fmaf(-aii, hi, kv));
        float nhi = fmaf(arr, hi, aii * hr);
        hr = nhr; hi = nhi;
        float g = __half2float(P16[r16 + 3072 + d]);
        float sil = g / (1.f + __expf(-g));
        float q = __half2float(P16[r16 + d]);
        yh[(row0 + t) * Dz + d] = __float2half_rn(q * hr * sil);
    }
}

// LN1: fp16 main + fp32 residual -> fp16 out only
__global__ __launch_bounds__(256) void add_ln_h(
    const __half* __restrict__ xh16, const float* __restrict__ res,
    const float* __restrict__ scale, const float* __restrict__ bias,
    __half* __restrict__ oh)
{
    __shared__ float red[8];
    int row = blockIdx.x, tid = threadIdx.x;
    const __half* xr = xh16 + (size_t)row * Dz;
    const float* rr = res + (size_t)row * Dz;
    float vals[4], sum = 0.f;
#pragma unroll
    for (int j = 0; j < 4; j++) {
        vals[j] = __half2float(xr[tid + j * 256]) + rr[tid + j * 256];
        sum += vals[j];
    }
#pragma unroll
    for (int o = 16; o > 0; o >>= 1) sum += __shfl_xor_sync(~0u, sum, o);
    if ((tid & 31) == 0) red[tid >> 5] = sum;
    __syncthreads();
    float tot = 0.f;
#pragma unroll
    for (int w = 0; w < 8; w++) tot += red[w];
    float mean = tot * (1.f / Dz);
    float vs = 0.f;
#pragma unroll
    for (int j = 0; j < 4; j++) { float dd = vals[j] - mean; vs += dd * dd; }
#pragma unroll
    for (int o = 16; o > 0; o >>= 1) vs += __shfl_xor_sync(~0u, vs, o);
    __syncthreads();
    if ((tid & 31) == 0) red[tid >> 5] = vs;
    __syncthreads();
    float vt = 0.f;
#pragma unroll
    for (int w = 0; w < 8; w++) vt += red[w];
    float rstd = rsqrtf(vt * (1.f / Dz) + 1e-6f);
#pragma unroll
    for (int j = 0; j < 4; j++) {
        int col = tid + j * 256;
        float v = (vals[j] - mean) * rstd * scale[col] + bias[col];
        oh[(size_t)row * Dz + col] = __float2half_rn(v);
    }
}

// LN2: fp16 main + fp16 residual -> fp32 out
__global__ __launch_bounds__(256) void add_ln_hh(
    const __half* __restrict__ xh16, const __half* __restrict__ res16,
    const float* __restrict__ scale, const float* __restrict__ bias,
    float* __restrict__ out)
{
    __shared__ float red[8];
    int row = blockIdx.x, tid = threadIdx.x;
    const __half* xr = xh16 + (size_t)row * Dz;
    const __half* rr = res16 + (size_t)row * Dz;
    float vals[4], sum = 0.f;
#pragma unroll
    for (int j = 0; j < 4; j++) {
        int col = tid + j * 256;
        vals[j] = __half2float(xr[col]) + __half2float(rr[col]);
        sum += vals[j];
    }
#pragma unroll
    for (int o = 16; o > 0; o >>= 1) sum += __shfl_xor_sync(~0u, sum, o);
    if ((tid & 31) == 0) red[tid >> 5] = sum;
    __syncthreads();
    float tot = 0.f;
#pragma unroll
    for (int w = 0; w < 8; w++) tot += red[w];
    float mean = tot * (1.f / Dz);
    float vs = 0.f;
#pragma unroll
    for (int j = 0; j < 4; j++) { float dd = vals[j] - mean; vs += dd * dd; }
#pragma unroll
    for (int o = 16; o > 0; o >>= 1) vs += __shfl_xor_sync(~0u, vs, o);
    __syncthreads();
    if ((tid & 31) == 0) red[tid >> 5] = vs;
    __syncthreads();
    float vt = 0.f;
#pragma unroll
    for (int w = 0; w < 8; w++) vt += red[w];
    float rstd = rsqrtf(vt * (1.f / Dz) + 1e-6f);
#pragma unroll
    for (int j = 0; j < 4; j++) {
        int col = tid + j * 256;
        out[(size_t)row * Dz + col] = (vals[j] - mean) * rstd * scale[col] + bias[col];
    }
}

// ------------------------- host ------------------------------------------
static void rungemm(const __half* Ah, const __half* Bh, int Nblk, int K,
                    const float* bias,
                    float* Cf, int ldcf, __half* Ch, int ldch, int choff, int split,
                    int act, int mode) {
    dim3 g(Nblk / 128, Mz / 128);
    gemm_mma<<<g, 128, GEMM_SMEM>>>(Ah, Bh, bias, Cf, ldcf, Ch, ldch, choff, split, K, act, mode);
}

extern "C" void kernel_launch(void* const* d_in, const int* in_sizes, int n_in,
                              void* d_out, int out_size)
{
    const float* x    = (const float*)d_in[0];
    const float* Wq   = (const float*)d_in[1];
    const float* Wk   = (const float*)d_in[2];
    const float* Wv   = (const float*)d_in[3];
    const float* Wa   = (const float*)d_in[4];
    const float* Wg   = (const float*)d_in[5];
    const float* Wo   = (const float*)d_in[6];
    const float* ln1s = (const float*)d_in[7];
    const float* ln1b = (const float*)d_in[8];
    const float* W1   = (const float*)d_in[9];
    const float* b1   = (const float*)d_in[10];
    const float* W2   = (const float*)d_in[11];
    const float* b2   = (const float*)d_in[12];
    const float* ln2s = (const float*)d_in[13];
    const float* ln2b = (const float*)d_in[14];
    float* out = (float*)d_out;

    static int inited = 0;
    if (!inited) {
        cudaFuncSetAttribute(gemm_mma, cudaFuncAttributeMaxDynamicSharedMemorySize, GEMM_SMEM);
        inited = 1;
    }

    float *Pa;
    __half *P16, *Yoh, *O2h, *xh, *yh, *uh, *Hh, *Wc, *WoP, *W1P, *W2P;
    cudaGetSymbolAddress((void**)&P16, g_P16);
    cudaGetSymbolAddress((void**)&Pa,  g_Pa);
    cudaGetSymbolAddress((void**)&Yoh, g_Yoh);
    cudaGetSymbolAddress((void**)&O2h, g_O2h);
    cudaGetSymbolAddress((void**)&xh, g_xh);
    cudaGetSymbolAddress((void**)&yh, g_yh);
    cudaGetSymbolAddress((void**)&uh, g_uh);
    cudaGetSymbolAddress((void**)&Hh, g_Hh);
    cudaGetSymbolAddress((void**)&Wc,  g_Wc);
    cudaGetSymbolAddress((void**)&WoP, g_Wo);
    cudaGetSymbolAddress((void**)&W1P, g_W1);
    cudaGetSymbolAddress((void**)&W2P, g_W2);

    WJobs js;
    js.j[0] = { Wq, Wc,                       Dz, Dz,     0 };
    js.j[1] = { Wk, Wc + 1024 * 1024,         Dz, Dz,     1024 };
    js.j[2] = { Wv, Wc + 2048 * 1024,         Dz, Dz,     2048 };
    js.j[3] = { Wa, Wc + 3072 * 1024,         Dz, 2 * Dz, 3072 };
    js.j[4] = { Wg, Wc + (size_t)5120 * 1024, Dz, Dz,     5120 };
    js.j[5] = { Wo, WoP, Dz, Dz,  6144 };
    js.j[6] = { W1, W1P, Dz, Fz,  7168 };
    js.j[7] = { W2, W2P, Fz, Dz, 11264 };
    wconv_all<<<15360, dim3(32, 8)>>>(js);                                      // 0
    conv_h<<<(Mz * Dz / 4 + 255) / 256, 256>>>(x, xh, (size_t)Mz * Dz / 4);     // 1
    rungemm(xh, Wc, 6144, Dz, nullptr, Pa, 0, P16, 0, 0, 0, 0, 3);              // 2
    scan_p1<<<1024, 256>>>(P16, Pa);                                            // 3
    scan_p2<<<8, 256>>>();                                                      // 4
    scan_p3<<<1024, 256>>>(P16, Pa, yh);                                        // 5
    rungemm(yh, WoP, 1024, Dz, nullptr, nullptr, 0, Yoh, 1024, 0, 0, 0, 0);     // 6
    add_ln_h<<<Mz, 256>>>(Yoh, x, ln1s, ln1b, uh);                              // 7
    rungemm(uh, W1P, 4096, Dz, b1, nullptr, 0, Hh, 4096, 0, 0, 2, 0);           // 8
    rungemm(Hh, W2P, 1024, Fz, b2, nullptr, 0, O2h, 1024, 0, 0, 1, 0);          // 9
    add_ln_hh<<<Mz, 256>>>(O2h, uh, ln2s, ln2b, out);                           // 10
}